// round 1
// baseline (speedup 1.0000x reference)
#include <cuda_runtime.h>

#define C   512
#define SP  4096
#define NH  8
#define HD  64
#define NB  2
#define SCALE 0.125f   // 1/sqrt(64)

// Scratch (allocation-free rule: static __device__ arrays)
__device__ float g_Q[NB * C * SP];
__device__ float g_K[NB * C * SP];
__device__ float g_V[NB * C * SP];
__device__ float g_AO[NB * C * SP];

// ---------------------------------------------------------------------------
// Kernel 1: fused QKV projection.  Out[o][s] = sum_c W[o][c] * X[c][s] + b[o]
// M=512(o), N=4096(s), K=512(c). 128x128 tile, 8x8 microtile, k-step 8.
// blockIdx.z = n*3 + which
// ---------------------------------------------------------------------------
__global__ __launch_bounds__(256) void proj_qkv_kernel(
    const float* __restrict__ x,
    const float* __restrict__ Wq, const float* __restrict__ bq,
    const float* __restrict__ Wk, const float* __restrict__ bk,
    const float* __restrict__ Wv, const float* __restrict__ bv)
{
    __shared__ float as[8][128];
    __shared__ float bs[8][128];

    const int which = blockIdx.z % 3;
    const int n     = blockIdx.z / 3;
    const float* W    = (which == 0) ? Wq : (which == 1) ? Wk : Wv;
    const float* bias = (which == 0) ? bq : (which == 1) ? bk : bv;
    float* out = ((which == 0) ? g_Q : (which == 1) ? g_K : g_V) + (size_t)n * C * SP;
    const float* X = x + (size_t)n * C * SP;

    const int o0 = blockIdx.y * 128;
    const int s0 = blockIdx.x * 128;
    const int tid = threadIdx.x;
    const int ty = tid >> 4, tx = tid & 15;

    const int lo  = tid >> 1;          // 0..127 (oo for A tile)
    const int lk4 = (tid & 1) * 4;     // 0 or 4
    const int bkr = tid >> 5;          // 0..7 (kk for B tile)
    const int bs4 = (tid & 31) * 4;    // 0..124

    float acc[8][8];
#pragma unroll
    for (int i = 0; i < 8; i++)
#pragma unroll
        for (int j = 0; j < 8; j++) acc[i][j] = 0.f;

    for (int c0 = 0; c0 < C; c0 += 8) {
        float4 wa = *(const float4*)(W + (size_t)(o0 + lo) * C + c0 + lk4);
        as[lk4 + 0][lo] = wa.x;
        as[lk4 + 1][lo] = wa.y;
        as[lk4 + 2][lo] = wa.z;
        as[lk4 + 3][lo] = wa.w;
        *(float4*)&bs[bkr][bs4] = *(const float4*)(X + (size_t)(c0 + bkr) * SP + s0 + bs4);
        __syncthreads();
#pragma unroll
        for (int kk = 0; kk < 8; kk++) {
            float4 a0 = *(float4*)&as[kk][ty * 8];
            float4 a1 = *(float4*)&as[kk][ty * 8 + 4];
            float4 b0 = *(float4*)&bs[kk][tx * 8];
            float4 b1 = *(float4*)&bs[kk][tx * 8 + 4];
            float a[8] = {a0.x, a0.y, a0.z, a0.w, a1.x, a1.y, a1.z, a1.w};
            float b[8] = {b0.x, b0.y, b0.z, b0.w, b1.x, b1.y, b1.z, b1.w};
#pragma unroll
            for (int i = 0; i < 8; i++)
#pragma unroll
                for (int j = 0; j < 8; j++)
                    acc[i][j] = fmaf(a[i], b[j], acc[i][j]);
        }
        __syncthreads();
    }

#pragma unroll
    for (int i = 0; i < 8; i++) {
        int o = o0 + ty * 8 + i;
        float bi = bias[o];
        float4 r0 = make_float4(acc[i][0] + bi, acc[i][1] + bi, acc[i][2] + bi, acc[i][3] + bi);
        float4 r1 = make_float4(acc[i][4] + bi, acc[i][5] + bi, acc[i][6] + bi, acc[i][7] + bi);
        *(float4*)(out + (size_t)o * SP + s0 + tx * 8)     = r0;
        *(float4*)(out + (size_t)o * SP + s0 + tx * 8 + 4) = r1;
    }
}

// ---------------------------------------------------------------------------
// Kernel 2: flash attention per (n,h). CTA = 64 query rows, stream 64-wide
// key blocks with online softmax. Q/K/V are channel-major [d=64][S].
// smem: qs[64][64] (d-major), kt[64][64] (d-major), vt[64][65] (t-major,
// stride 65 to cap bank conflicts at 2-way), ps[64][68].
// ---------------------------------------------------------------------------
__global__ __launch_bounds__(256) void attn_kernel()
{
    extern __shared__ float sm[];
    float* qs = sm;                          // 64*64
    float* kt = sm + 64 * 64;                // 64*64
    float* vt = sm + 2 * 64 * 64;            // 64*65
    float* ps = sm + 2 * 64 * 64 + 64 * 65;  // 64*68

    const int nh = blockIdx.y;
    const int n = nh >> 3, h = nh & 7;
    const float* Qh = g_Q + ((size_t)n * C + h * HD) * SP;
    const float* Kh = g_K + ((size_t)n * C + h * HD) * SP;
    const float* Vh = g_V + ((size_t)n * C + h * HD) * SP;
    float*       Oh = g_AO + ((size_t)n * C + h * HD) * SP;
    const int s0 = blockIdx.x * 64;

    const int tid = threadIdx.x;
    const int ty = tid >> 4, tx = tid & 15;
    const int ldd = tid >> 4;          // 0..15
    const int lc4 = (tid & 15) * 4;    // 0..60

    // Load Q tile (pre-scaled)
#pragma unroll
    for (int i = 0; i < 4; i++) {
        int dd = ldd + i * 16;
        float4 v = *(const float4*)(Qh + (size_t)dd * SP + s0 + lc4);
        v.x *= SCALE; v.y *= SCALE; v.z *= SCALE; v.w *= SCALE;
        *(float4*)&qs[dd * 64 + lc4] = v;
    }

    float m_i[4], l_i[4], o_acc[4][4];
#pragma unroll
    for (int i = 0; i < 4; i++) {
        m_i[i] = -1e30f; l_i[i] = 0.f;
#pragma unroll
        for (int j = 0; j < 4; j++) o_acc[i][j] = 0.f;
    }
    __syncthreads();

    for (int t0 = 0; t0 < SP; t0 += 64) {
        // load K (d-major) and V (transposed to t-major)
#pragma unroll
        for (int i = 0; i < 4; i++) {
            int dd = ldd + i * 16;
            *(float4*)&kt[dd * 64 + lc4] = *(const float4*)(Kh + (size_t)dd * SP + t0 + lc4);
            float4 vv = *(const float4*)(Vh + (size_t)dd * SP + t0 + lc4);
            vt[(lc4 + 0) * 65 + dd] = vv.x;
            vt[(lc4 + 1) * 65 + dd] = vv.y;
            vt[(lc4 + 2) * 65 + dd] = vv.z;
            vt[(lc4 + 3) * 65 + dd] = vv.w;
        }
        __syncthreads();

        // GEMM1: S[s][t] = sum_d q[d][s]*k[d][t]
        float sacc[4][4];
#pragma unroll
        for (int i = 0; i < 4; i++)
#pragma unroll
            for (int j = 0; j < 4; j++) sacc[i][j] = 0.f;

#pragma unroll 8
        for (int dd = 0; dd < 64; dd++) {
            float4 qv = *(float4*)&qs[dd * 64 + ty * 4];
            float4 kv = *(float4*)&kt[dd * 64 + tx * 4];
            float q4[4] = {qv.x, qv.y, qv.z, qv.w};
            float k4[4] = {kv.x, kv.y, kv.z, kv.w};
#pragma unroll
            for (int i = 0; i < 4; i++)
#pragma unroll
                for (int j = 0; j < 4; j++)
                    sacc[i][j] = fmaf(q4[i], k4[j], sacc[i][j]);
        }

        // online softmax; rows 4*ty+i spread across 16 tx lanes (contiguous
        // 16-lane groups in the warp, so xor-shfl over 8/4/2/1 stays in-group)
#pragma unroll
        for (int i = 0; i < 4; i++) {
            float rm = fmaxf(fmaxf(sacc[i][0], sacc[i][1]), fmaxf(sacc[i][2], sacc[i][3]));
#pragma unroll
            for (int off = 8; off > 0; off >>= 1)
                rm = fmaxf(rm, __shfl_xor_sync(0xffffffffu, rm, off));
            float mnew  = fmaxf(m_i[i], rm);
            float alpha = __expf(m_i[i] - mnew);
            float rs = 0.f;
#pragma unroll
            for (int j = 0; j < 4; j++) {
                sacc[i][j] = __expf(sacc[i][j] - mnew);
                rs += sacc[i][j];
            }
#pragma unroll
            for (int off = 8; off > 0; off >>= 1)
                rs += __shfl_xor_sync(0xffffffffu, rs, off);
            l_i[i] = l_i[i] * alpha + rs;
            m_i[i] = mnew;
#pragma unroll
            for (int j = 0; j < 4; j++) o_acc[i][j] *= alpha;
            *(float4*)&ps[(ty * 4 + i) * 68 + tx * 4] =
                make_float4(sacc[i][0], sacc[i][1], sacc[i][2], sacc[i][3]);
        }
        __syncthreads();

        // GEMM2: O[s][d] += sum_t P[s][t] * V[t][d]
#pragma unroll 8
        for (int tt = 0; tt < 64; tt++) {
            float pv[4], vv[4];
#pragma unroll
            for (int i = 0; i < 4; i++) pv[i] = ps[(ty * 4 + i) * 68 + tt];
#pragma unroll
            for (int j = 0; j < 4; j++) vv[j] = vt[tt * 65 + tx * 4 + j];
#pragma unroll
            for (int i = 0; i < 4; i++)
#pragma unroll
                for (int j = 0; j < 4; j++)
                    o_acc[i][j] = fmaf(pv[i], vv[j], o_acc[i][j]);
        }
        __syncthreads();
    }

    // normalize + transpose through smem for coalesced channel-major stores
#pragma unroll
    for (int i = 0; i < 4; i++) {
        float inv = 1.0f / l_i[i];
#pragma unroll
        for (int j = 0; j < 4; j++)
            qs[(tx * 4 + j) * 64 + ty * 4 + i] = o_acc[i][j] * inv;
    }
    __syncthreads();
#pragma unroll
    for (int i = 0; i < 4; i++) {
        int dd = ldd + i * 16;
        *(float4*)(Oh + (size_t)dd * SP + s0 + lc4) = *(float4*)&qs[dd * 64 + lc4];
    }
}

// ---------------------------------------------------------------------------
// Kernel 3: output projection + residual.
// out[n][o][s] = gamma * (sum_c Wo[o][c]*AO[n][c][s] + bo[o]) + x[n][o][s]
// ---------------------------------------------------------------------------
__global__ __launch_bounds__(256) void proj_out_kernel(
    const float* __restrict__ x, const float* __restrict__ Wo,
    const float* __restrict__ bo, const float* __restrict__ gamma,
    float* __restrict__ out)
{
    __shared__ float as[8][128];
    __shared__ float bs[8][128];

    const int n = blockIdx.z;
    const float* X = g_AO + (size_t)n * C * SP;
    const int o0 = blockIdx.y * 128;
    const int s0 = blockIdx.x * 128;
    const int tid = threadIdx.x;
    const int ty = tid >> 4, tx = tid & 15;

    const int lo  = tid >> 1;
    const int lk4 = (tid & 1) * 4;
    const int bkr = tid >> 5;
    const int bs4 = (tid & 31) * 4;

    float acc[8][8];
#pragma unroll
    for (int i = 0; i < 8; i++)
#pragma unroll
        for (int j = 0; j < 8; j++) acc[i][j] = 0.f;

    for (int c0 = 0; c0 < C; c0 += 8) {
        float4 wa = *(const float4*)(Wo + (size_t)(o0 + lo) * C + c0 + lk4);
        as[lk4 + 0][lo] = wa.x;
        as[lk4 + 1][lo] = wa.y;
        as[lk4 + 2][lo] = wa.z;
        as[lk4 + 3][lo] = wa.w;
        *(float4*)&bs[bkr][bs4] = *(const float4*)(X + (size_t)(c0 + bkr) * SP + s0 + bs4);
        __syncthreads();
#pragma unroll
        for (int kk = 0; kk < 8; kk++) {
            float4 a0 = *(float4*)&as[kk][ty * 8];
            float4 a1 = *(float4*)&as[kk][ty * 8 + 4];
            float4 b0 = *(float4*)&bs[kk][tx * 8];
            float4 b1 = *(float4*)&bs[kk][tx * 8 + 4];
            float a[8] = {a0.x, a0.y, a0.z, a0.w, a1.x, a1.y, a1.z, a1.w};
            float b[8] = {b0.x, b0.y, b0.z, b0.w, b1.x, b1.y, b1.z, b1.w};
#pragma unroll
            for (int i = 0; i < 8; i++)
#pragma unroll
                for (int j = 0; j < 8; j++)
                    acc[i][j] = fmaf(a[i], b[j], acc[i][j]);
        }
        __syncthreads();
    }

    const float g = gamma[0];
#pragma unroll
    for (int i = 0; i < 8; i++) {
        int o = o0 + ty * 8 + i;
        float bi = bo[o];
        size_t base = ((size_t)n * C + o) * SP + s0 + tx * 8;
        float4 x0 = *(const float4*)(x + base);
        float4 x1 = *(const float4*)(x + base + 4);
        float4 r0 = make_float4(g * (acc[i][0] + bi) + x0.x,
                                g * (acc[i][1] + bi) + x0.y,
                                g * (acc[i][2] + bi) + x0.z,
                                g * (acc[i][3] + bi) + x0.w);
        float4 r1 = make_float4(g * (acc[i][4] + bi) + x1.x,
                                g * (acc[i][5] + bi) + x1.y,
                                g * (acc[i][6] + bi) + x1.z,
                                g * (acc[i][7] + bi) + x1.w);
        *(float4*)(out + base)     = r0;
        *(float4*)(out + base + 4) = r1;
    }
}

// ---------------------------------------------------------------------------
extern "C" void kernel_launch(void* const* d_in, const int* in_sizes, int n_in,
                              void* d_out, int out_size)
{
    const float* x     = (const float*)d_in[0];
    const float* Wq    = (const float*)d_in[1];
    const float* bq    = (const float*)d_in[2];
    const float* Wk    = (const float*)d_in[3];
    const float* bk    = (const float*)d_in[4];
    const float* Wv    = (const float*)d_in[5];
    const float* bv    = (const float*)d_in[6];
    const float* Wo    = (const float*)d_in[7];
    const float* bo    = (const float*)d_in[8];
    const float* gamma = (const float*)d_in[9];
    float* out = (float*)d_out;

    dim3 g1(SP / 128, C / 128, 3 * NB);
    proj_qkv_kernel<<<g1, 256>>>(x, Wq, bq, Wk, bk, Wv, bv);

    const int attn_smem = (64 * 64 * 2 + 64 * 65 + 64 * 68) * (int)sizeof(float);
    cudaFuncSetAttribute(attn_kernel, cudaFuncAttributeMaxDynamicSharedMemorySize, attn_smem);
    dim3 g2(SP / 64, NB * NH);
    attn_kernel<<<g2, 256, attn_smem>>>();

    dim3 g3(SP / 128, C / 128, NB);
    proj_out_kernel<<<g3, 256>>>(x, Wo, bo, gamma, out);
}

// round 2
// speedup vs baseline: 5.9478x; 5.9478x over previous
#include <cuda_runtime.h>
#include <cuda_fp16.h>
#include <cstdint>

#define C    512
#define SP   4096
#define NH   8
#define HD   64
#define NB   2
// fold softmax scale and log2(e) into Q projection; softmax uses exp2
#define QS   (0.125f * 1.44269504088896f)

// fp16 scratch (allocation-free rule: __device__ globals)
__device__ __half g_xh [NB * SP * C];          // x transposed: [n][s][c]
__device__ __half g_Wh [4 * C * C];            // Wq(scaled),Wk,Wv,Wo as [o][c]
__device__ __half g_Qh [NB * NH * SP * HD];    // [nh][s][d] (scaled)
__device__ __half g_Kh [NB * NH * SP * HD];    // [nh][s][d]
__device__ __half g_Vh [NB * NH * HD * SP];    // [nh][d][s]
__device__ __half g_AOh[NB * NH * SP * HD];    // [nh][s][d]

// ---------------------------------------------------------------- helpers
__device__ __forceinline__ uint32_t cvta_s(const void* p) {
    return (uint32_t)__cvta_generic_to_shared(p);
}
__device__ __forceinline__ void cp16(uint32_t s, const void* g) {
    asm volatile("cp.async.cg.shared.global [%0], [%1], 16;\n" ::"r"(s), "l"(g));
}
#define CP_COMMIT asm volatile("cp.async.commit_group;\n" ::)
#define CP_WAIT(n) asm volatile("cp.async.wait_group %0;\n" ::"n"(n))

__device__ __forceinline__ void ldsm4(uint32_t a[4], uint32_t addr) {
    asm volatile("ldmatrix.sync.aligned.m8n8.x4.shared.b16 {%0,%1,%2,%3}, [%4];"
                 : "=r"(a[0]), "=r"(a[1]), "=r"(a[2]), "=r"(a[3]) : "r"(addr));
}
// D += A * B, fp16 in, fp32 accum
__device__ __forceinline__ void mma16816(float c[4], const uint32_t a[4],
                                         uint32_t b0, uint32_t b1) {
    asm volatile(
        "mma.sync.aligned.m16n8k16.row.col.f32.f16.f16.f32 "
        "{%0,%1,%2,%3},{%4,%5,%6,%7},{%8,%9},{%0,%1,%2,%3};"
        : "+f"(c[0]), "+f"(c[1]), "+f"(c[2]), "+f"(c[3])
        : "r"(a[0]), "r"(a[1]), "r"(a[2]), "r"(a[3]), "r"(b0), "r"(b1));
}
// one formula for A-frags and Bt-frags: base(bytes), r0/c0/stride in halves
__device__ __forceinline__ uint32_t lds_addr(uint32_t base, int r0, int c0, int stride) {
    int lane = threadIdx.x & 31;
    return base + (uint32_t)(((r0 + (lane & 15)) * stride + c0 + ((lane >> 4) << 3)) * 2);
}
__device__ __forceinline__ float ex2f(float x) {
    float y; asm("ex2.approx.ftz.f32 %0, %1;" : "=f"(y) : "f"(x)); return y;
}
__device__ __forceinline__ uint32_t packh2(float lo, float hi) {
    __half2 h = __floats2half2_rn(lo, hi);
    uint32_t r; memcpy(&r, &h, 4); return r;
}

// ---------------------------------------------------------------- converts
__global__ __launch_bounds__(256) void convert_w_kernel(
    const float* __restrict__ Wq, const float* __restrict__ Wk,
    const float* __restrict__ Wv, const float* __restrict__ Wo)
{
    int i = blockIdx.x * 256 + threadIdx.x;          // 4*C*C total
    int which = i >> 18;                              // C*C = 2^18
    int j = i & (C * C - 1);
    const float* src = (which == 0) ? Wq : (which == 1) ? Wk : (which == 2) ? Wv : Wo;
    float v = src[j] * (which == 0 ? QS : 1.0f);
    g_Wh[i] = __float2half_rn(v);
}

__global__ __launch_bounds__(256) void transpose_x_kernel(const float* __restrict__ x)
{
    __shared__ float t[32][33];
    int n = blockIdx.z, s0 = blockIdx.x * 32, c0 = blockIdx.y * 32;
#pragma unroll
    for (int k = 0; k < 4; k++) {
        int idx = threadIdx.x + k * 256;
        int c = idx >> 5, s = idx & 31;
        t[c][s] = x[((size_t)n * C + c0 + c) * SP + s0 + s];
    }
    __syncthreads();
#pragma unroll
    for (int k = 0; k < 4; k++) {
        int idx = threadIdx.x + k * 256;
        int s = idx >> 5, c = idx & 31;
        g_xh[((size_t)n * SP + s0 + s) * C + c0 + c] = __float2half_rn(t[c][s]);
    }
}

// ---------------------------------------------------------------- QKV proj
// Out[s][o] = sum_c xT[s][c] * W[o][c];  BM=256(s) BN=64(o) BK=32
// smem: A[2][256][40], B[2][64][40] halves (pad 8 -> ldmatrix conflict-free)
__global__ __launch_bounds__(256, 2) void proj_qkv_kernel(
    const float* __restrict__ bq, const float* __restrict__ bk,
    const float* __restrict__ bv)
{
    extern __shared__ __half sm[];
    __half* As[2] = { sm, sm + 256 * 40 };
    __half* Bs[2] = { sm + 2 * 256 * 40, sm + 2 * 256 * 40 + 64 * 40 };

    const int which = blockIdx.z % 3, n = blockIdx.z / 3;
    const int s0 = blockIdx.x * 256, o0 = blockIdx.y * 64;
    const int tid = threadIdx.x, w = tid >> 5, lane = tid & 31;

    const __half* Ag = g_xh + ((size_t)n * SP + s0) * C;
    const __half* Bg = g_Wh + (size_t)which * C * C + (size_t)o0 * C;

    float acc[2][8][4];
#pragma unroll
    for (int a = 0; a < 2; a++)
#pragma unroll
        for (int b = 0; b < 8; b++)
#pragma unroll
            for (int c = 0; c < 4; c++) acc[a][b][c] = 0.f;

    auto load_tiles = [&](int buf, int c0) {
        const __half* ga = Ag + (size_t)tid * C + c0;
        uint32_t sa = cvta_s(As[buf] + tid * 40);
        cp16(sa, ga); cp16(sa + 16, ga + 8); cp16(sa + 32, ga + 16); cp16(sa + 48, ga + 24);
        int r = tid >> 2, ch = tid & 3;
        cp16(cvta_s(Bs[buf] + r * 40 + ch * 8), Bg + (size_t)r * C + c0 + ch * 8);
    };

    load_tiles(0, 0);
    CP_COMMIT;
    int buf = 0;
    for (int kb = 0; kb < 16; kb++) {
        if (kb < 15) { load_tiles(buf ^ 1, (kb + 1) * 32); CP_COMMIT; }
        if (kb < 15) CP_WAIT(1); else CP_WAIT(0);
        __syncthreads();
        uint32_t ab = cvta_s(As[buf]), bb = cvta_s(Bs[buf]);
#pragma unroll
        for (int ks = 0; ks < 2; ks++) {
            uint32_t Af[2][4], Bf[4][4];
#pragma unroll
            for (int mt = 0; mt < 2; mt++)
                ldsm4(Af[mt], lds_addr(ab, w * 32 + mt * 16, ks * 16, 40));
#pragma unroll
            for (int nt = 0; nt < 4; nt++)
                ldsm4(Bf[nt], lds_addr(bb, nt * 16, ks * 16, 40));
#pragma unroll
            for (int mt = 0; mt < 2; mt++)
#pragma unroll
                for (int nt = 0; nt < 4; nt++) {
                    mma16816(acc[mt][2 * nt],     Af[mt], Bf[nt][0], Bf[nt][2]);
                    mma16816(acc[mt][2 * nt + 1], Af[mt], Bf[nt][1], Bf[nt][3]);
                }
        }
        __syncthreads();
        buf ^= 1;
    }

    const float* bias = (which == 0) ? bq : (which == 1) ? bk : bv;
    const float bsc = (which == 0) ? QS : 1.0f;
    const int h = o0 >> 6;
    __half* outQK = (which == 0) ? g_Qh : g_Kh;
#pragma unroll
    for (int mt = 0; mt < 2; mt++)
#pragma unroll
        for (int f = 0; f < 8; f++) {
            int srow = s0 + w * 32 + mt * 16 + (lane >> 2);
            int o = o0 + f * 8 + (lane & 3) * 2;
            int d = o & 63;
            float b0 = bias[o] * bsc, b1 = bias[o + 1] * bsc;
            float v00 = acc[mt][f][0] + b0, v01 = acc[mt][f][1] + b1;
            float v10 = acc[mt][f][2] + b0, v11 = acc[mt][f][3] + b1;
            if (which < 2) {
                size_t base = ((size_t)(n * NH + h) * SP + srow) * 64 + d;
                *(__half2*)(outQK + base)            = __floats2half2_rn(v00, v01);
                *(__half2*)(outQK + base + 8 * 64)   = __floats2half2_rn(v10, v11);
            } else {
                size_t base = ((size_t)(n * NH + h) * 64 + d) * SP + srow;
                g_Vh[base]          = __float2half_rn(v00);
                g_Vh[base + SP]     = __float2half_rn(v01);
                g_Vh[base + 8]      = __float2half_rn(v10);
                g_Vh[base + SP + 8] = __float2half_rn(v11);
            }
        }
}

// ---------------------------------------------------------------- attention
// CTA: 128 q-rows of one (n,h); 8 warps x 16 rows; 64-key tiles, cp.async x2
__global__ __launch_bounds__(256, 2) void attn_kernel()
{
    extern __shared__ __half sm[];
    __half* Qs    = sm;                                   // 128*72
    __half* Ks[2] = { sm + 9216, sm + 9216 + 4608 };      // 64*72 each
    __half* Vs[2] = { sm + 18432, sm + 18432 + 4608 };

    const int tid = threadIdx.x, w = tid >> 5, lane = tid & 31;
    const int nh = blockIdx.y;
    const int q0 = blockIdx.x * 128;
    const __half* Qg = g_Qh + ((size_t)nh * SP + q0) * 64;
    const __half* Kg = g_Kh + (size_t)nh * SP * 64;
    const __half* Vg = g_Vh + (size_t)nh * 64 * SP;

    // Q: 128 rows x 128B = 1024 x 16B chunks
#pragma unroll
    for (int i = 0; i < 4; i++) {
        int idx = tid + i * 256, r = idx >> 3, ch = idx & 7;
        cp16(cvta_s(Qs + r * 72 + ch * 8), Qg + (size_t)r * 64 + ch * 8);
    }
    CP_COMMIT;

    auto load_kv = [&](int buf, int t0) {
#pragma unroll
        for (int i = 0; i < 2; i++) {
            int idx = tid + i * 256, r = idx >> 3, ch = idx & 7;
            cp16(cvta_s(Ks[buf] + r * 72 + ch * 8), Kg + ((size_t)(t0 + r)) * 64 + ch * 8);
            cp16(cvta_s(Vs[buf] + r * 72 + ch * 8), Vg + (size_t)r * SP + t0 + ch * 8);
        }
    };
    load_kv(0, 0);
    CP_COMMIT;

    float O[8][4];
#pragma unroll
    for (int f = 0; f < 8; f++)
#pragma unroll
        for (int e = 0; e < 4; e++) O[f][e] = 0.f;
    float m0 = -1e30f, m1 = -1e30f, l0 = 0.f, l1 = 0.f;
    uint32_t Qa[4][4];

    int buf = 0;
    for (int it = 0; it < SP / 64; it++) {
        if (it < SP / 64 - 1) { load_kv(buf ^ 1, (it + 1) * 64); CP_COMMIT; }
        if (it < SP / 64 - 1) CP_WAIT(1); else CP_WAIT(0);
        __syncthreads();
        if (it == 0) {
            uint32_t qb = cvta_s(Qs);
#pragma unroll
            for (int ks = 0; ks < 4; ks++)
                ldsm4(Qa[ks], lds_addr(qb, w * 16, ks * 16, 72));
        }

        // GEMM1: S[16q][64k]
        float S[8][4];
#pragma unroll
        for (int f = 0; f < 8; f++)
#pragma unroll
            for (int e = 0; e < 4; e++) S[f][e] = 0.f;
        uint32_t kb = cvta_s(Ks[buf]);
#pragma unroll
        for (int ks = 0; ks < 4; ks++) {
            uint32_t Bf[4][4];
#pragma unroll
            for (int nt = 0; nt < 4; nt++)
                ldsm4(Bf[nt], lds_addr(kb, nt * 16, ks * 16, 72));
#pragma unroll
            for (int nt = 0; nt < 4; nt++) {
                mma16816(S[2 * nt],     Qa[ks], Bf[nt][0], Bf[nt][2]);
                mma16816(S[2 * nt + 1], Qa[ks], Bf[nt][1], Bf[nt][3]);
            }
        }

        // online softmax (logits already in log2 units)
        float rm0 = -1e30f, rm1 = -1e30f;
#pragma unroll
        for (int f = 0; f < 8; f++) {
            rm0 = fmaxf(rm0, fmaxf(S[f][0], S[f][1]));
            rm1 = fmaxf(rm1, fmaxf(S[f][2], S[f][3]));
        }
        rm0 = fmaxf(rm0, __shfl_xor_sync(0xffffffffu, rm0, 1));
        rm0 = fmaxf(rm0, __shfl_xor_sync(0xffffffffu, rm0, 2));
        rm1 = fmaxf(rm1, __shfl_xor_sync(0xffffffffu, rm1, 1));
        rm1 = fmaxf(rm1, __shfl_xor_sync(0xffffffffu, rm1, 2));
        float mn0 = fmaxf(m0, rm0), mn1 = fmaxf(m1, rm1);
        float a0 = ex2f(m0 - mn0), a1 = ex2f(m1 - mn1);
        m0 = mn0; m1 = mn1;
        float rs0 = 0.f, rs1 = 0.f;
#pragma unroll
        for (int f = 0; f < 8; f++) {
            S[f][0] = ex2f(S[f][0] - mn0); S[f][1] = ex2f(S[f][1] - mn0);
            S[f][2] = ex2f(S[f][2] - mn1); S[f][3] = ex2f(S[f][3] - mn1);
            rs0 += S[f][0] + S[f][1];
            rs1 += S[f][2] + S[f][3];
        }
        rs0 += __shfl_xor_sync(0xffffffffu, rs0, 1);
        rs0 += __shfl_xor_sync(0xffffffffu, rs0, 2);
        rs1 += __shfl_xor_sync(0xffffffffu, rs1, 1);
        rs1 += __shfl_xor_sync(0xffffffffu, rs1, 2);
        l0 = l0 * a0 + rs0; l1 = l1 * a1 + rs1;
#pragma unroll
        for (int f = 0; f < 8; f++) {
            O[f][0] *= a0; O[f][1] *= a0; O[f][2] *= a1; O[f][3] *= a1;
        }
        // P (fp32 C-frags) -> fp16 A-frags, in registers
        uint32_t Pa[4][4];
#pragma unroll
        for (int i = 0; i < 4; i++) {
            Pa[i][0] = packh2(S[2 * i][0],     S[2 * i][1]);
            Pa[i][1] = packh2(S[2 * i][2],     S[2 * i][3]);
            Pa[i][2] = packh2(S[2 * i + 1][0], S[2 * i + 1][1]);
            Pa[i][3] = packh2(S[2 * i + 1][2], S[2 * i + 1][3]);
        }

        // GEMM2: O[16q][64d] += P * V
        uint32_t vb = cvta_s(Vs[buf]);
#pragma unroll
        for (int kt = 0; kt < 4; kt++) {
            uint32_t Bf[4][4];
#pragma unroll
            for (int nt = 0; nt < 4; nt++)
                ldsm4(Bf[nt], lds_addr(vb, nt * 16, kt * 16, 72));
#pragma unroll
            for (int nt = 0; nt < 4; nt++) {
                mma16816(O[2 * nt],     Pa[kt], Bf[nt][0], Bf[nt][2]);
                mma16816(O[2 * nt + 1], Pa[kt], Bf[nt][1], Bf[nt][3]);
            }
        }
        __syncthreads();
        buf ^= 1;
    }

    float inv0 = 1.0f / l0, inv1 = 1.0f / l1;
    int r = lane >> 2;
#pragma unroll
    for (int f = 0; f < 8; f++) {
        int d = f * 8 + (lane & 3) * 2;
        int q = q0 + w * 16 + r;
        size_t base = ((size_t)nh * SP + q) * 64 + d;
        *(__half2*)(g_AOh + base)          = __floats2half2_rn(O[f][0] * inv0, O[f][1] * inv0);
        *(__half2*)(g_AOh + base + 8 * 64) = __floats2half2_rn(O[f][2] * inv1, O[f][3] * inv1);
    }
}

// ---------------------------------------------------------------- out proj
// Out[n][o][s] = gamma*(sum_c AO[s][c]*Wo[o][c] + bo[o]) + x[n][o][s]
__global__ __launch_bounds__(256, 2) void proj_out_kernel(
    const float* __restrict__ x, const float* __restrict__ bo,
    const float* __restrict__ gamma, float* __restrict__ out)
{
    extern __shared__ __half sm[];
    __half* As[2] = { sm, sm + 256 * 40 };
    __half* Bs[2] = { sm + 2 * 256 * 40, sm + 2 * 256 * 40 + 64 * 40 };

    const int n = blockIdx.z;
    const int s0 = blockIdx.x * 256, o0 = blockIdx.y * 64;
    const int tid = threadIdx.x, w = tid >> 5, lane = tid & 31;
    const __half* Bg = g_Wh + (size_t)3 * C * C + (size_t)o0 * C;

    float acc[2][8][4];
#pragma unroll
    for (int a = 0; a < 2; a++)
#pragma unroll
        for (int b = 0; b < 8; b++)
#pragma unroll
            for (int c = 0; c < 4; c++) acc[a][b][c] = 0.f;

    auto load_tiles = [&](int buf, int c0) {
        int hh = c0 >> 6, d0 = c0 & 63;
        const __half* ga = g_AOh + ((size_t)(n * NH + hh) * SP + s0 + tid) * 64 + d0;
        uint32_t sa = cvta_s(As[buf] + tid * 40);
        cp16(sa, ga); cp16(sa + 16, ga + 8); cp16(sa + 32, ga + 16); cp16(sa + 48, ga + 24);
        int r = tid >> 2, ch = tid & 3;
        cp16(cvta_s(Bs[buf] + r * 40 + ch * 8), Bg + (size_t)r * C + c0 + ch * 8);
    };

    load_tiles(0, 0);
    CP_COMMIT;
    int buf = 0;
    for (int kb = 0; kb < 16; kb++) {
        if (kb < 15) { load_tiles(buf ^ 1, (kb + 1) * 32); CP_COMMIT; }
        if (kb < 15) CP_WAIT(1); else CP_WAIT(0);
        __syncthreads();
        uint32_t ab = cvta_s(As[buf]), bb = cvta_s(Bs[buf]);
#pragma unroll
        for (int ks = 0; ks < 2; ks++) {
            uint32_t Af[2][4], Bf[4][4];
#pragma unroll
            for (int mt = 0; mt < 2; mt++)
                ldsm4(Af[mt], lds_addr(ab, w * 32 + mt * 16, ks * 16, 40));
#pragma unroll
            for (int nt = 0; nt < 4; nt++)
                ldsm4(Bf[nt], lds_addr(bb, nt * 16, ks * 16, 40));
#pragma unroll
            for (int mt = 0; mt < 2; mt++)
#pragma unroll
                for (int nt = 0; nt < 4; nt++) {
                    mma16816(acc[mt][2 * nt],     Af[mt], Bf[nt][0], Bf[nt][2]);
                    mma16816(acc[mt][2 * nt + 1], Af[mt], Bf[nt][1], Bf[nt][3]);
                }
        }
        __syncthreads();
        buf ^= 1;
    }

    const float g = gamma[0];
#pragma unroll
    for (int mt = 0; mt < 2; mt++)
#pragma unroll
        for (int f = 0; f < 8; f++) {
            int srow = s0 + w * 32 + mt * 16 + (lane >> 2);
            int o = o0 + f * 8 + (lane & 3) * 2;
            float b0 = bo[o], b1 = bo[o + 1];
            size_t p00 = ((size_t)n * C + o) * SP + srow;
            size_t p01 = p00 + SP;
            out[p00]     = g * (acc[mt][f][0] + b0) + x[p00];
            out[p01]     = g * (acc[mt][f][1] + b1) + x[p01];
            out[p00 + 8] = g * (acc[mt][f][2] + b0) + x[p00 + 8];
            out[p01 + 8] = g * (acc[mt][f][3] + b1) + x[p01 + 8];
        }
}

// ---------------------------------------------------------------- launch
extern "C" void kernel_launch(void* const* d_in, const int* in_sizes, int n_in,
                              void* d_out, int out_size)
{
    const float* x     = (const float*)d_in[0];
    const float* Wq    = (const float*)d_in[1];
    const float* bq    = (const float*)d_in[2];
    const float* Wk    = (const float*)d_in[3];
    const float* bk    = (const float*)d_in[4];
    const float* Wv    = (const float*)d_in[5];
    const float* bv    = (const float*)d_in[6];
    const float* Wo    = (const float*)d_in[7];
    const float* bo    = (const float*)d_in[8];
    const float* gamma = (const float*)d_in[9];
    float* out = (float*)d_out;

    const int proj_smem = (2 * 256 * 40 + 2 * 64 * 40) * 2;   // 51200 B
    const int attn_smem = (128 * 72 + 4 * 64 * 72) * 2;       // 55296 B
    cudaFuncSetAttribute(proj_qkv_kernel, cudaFuncAttributeMaxDynamicSharedMemorySize, proj_smem);
    cudaFuncSetAttribute(proj_out_kernel, cudaFuncAttributeMaxDynamicSharedMemorySize, proj_smem);
    cudaFuncSetAttribute(attn_kernel,     cudaFuncAttributeMaxDynamicSharedMemorySize, attn_smem);

    convert_w_kernel<<<4 * C * C / 256, 256>>>(Wq, Wk, Wv, Wo);
    transpose_x_kernel<<<dim3(SP / 32, C / 32, NB), 256>>>(x);
    proj_qkv_kernel<<<dim3(SP / 256, C / 64, 3 * NB), 256, proj_smem>>>(bq, bk, bv);
    attn_kernel<<<dim3(SP / 128, NB * NH), 256, attn_smem>>>();
    proj_out_kernel<<<dim3(SP / 256, C / 64, NB), 256, proj_smem>>>(x, bo, gamma, out);
}